// round 14
// baseline (speedup 1.0000x reference)
#include <cuda_runtime.h>
#include <cuda_fp16.h>
#include <math.h>
#include <float.h>
#include <stdint.h>

#define BB 16
#define LL 4096
#define NN 512
#define DD 256
#define EPSV 1e-8f

__device__ float g_pnorm[BB * NN];
__device__ float g_xnorm[BB * LL];
__device__ __half g_xh[BB * LL * DD];    // 32MB fp16 X
__device__ __half g_ph[BB * NN * DD];    // 4MB fp16 P [b][n][d]
__device__ __half g_pth[BB * DD * NN];   // 4MB fp16 P^T [b][d][n]

__device__ __forceinline__ uint32_t smem_u32(const void* p) {
    uint32_t a;
    asm("{ .reg .u64 t; cvta.to.shared.u64 t, %1; cvt.u32.u64 %0, t; }" : "=r"(a) : "l"(p));
    return a;
}
__device__ __forceinline__ void cp16(uint32_t dst, const void* src) {
    asm volatile("cp.async.ca.shared.global [%0], [%1], 16;" :: "r"(dst), "l"(src));
}
#define CP_COMMIT() asm volatile("cp.async.commit_group;" ::: "memory")
#define CP_WAIT1()  asm volatile("cp.async.wait_group 1;" ::: "memory")
#define CP_WAIT0()  asm volatile("cp.async.wait_group 0;" ::: "memory")

__device__ __forceinline__ void ldsm4(uint32_t* r, uint32_t addr) {
    asm volatile("ldmatrix.sync.aligned.m8n8.x4.shared.b16 {%0,%1,%2,%3}, [%4];"
        : "=r"(r[0]), "=r"(r[1]), "=r"(r[2]), "=r"(r[3]) : "r"(addr));
}

__device__ __forceinline__ void mma_f16(float* d, const uint32_t* a, const uint32_t* b) {
    asm volatile(
        "mma.sync.aligned.m16n8k16.row.col.f32.f16.f16.f32 "
        "{%0,%1,%2,%3}, {%4,%5,%6,%7}, {%8,%9}, {%0,%1,%2,%3};"
        : "+f"(d[0]), "+f"(d[1]), "+f"(d[2]), "+f"(d[3])
        : "r"(a[0]), "r"(a[1]), "r"(a[2]), "r"(a[3]), "r"(b[0]), "r"(b[1]));
}

// ---------------- prepasses ----------------
__global__ void cvtx_kernel(const float* __restrict__ x) {
    int w = (blockIdx.x * blockDim.x + threadIdx.x) >> 5;
    int lane = threadIdx.x & 31;
    if (w >= BB * LL) return;
    const float4* src = (const float4*)(x + (size_t)w * DD);
    float4 v0 = src[lane], v1 = src[lane + 32];
    float s = v0.x * v0.x + v0.y * v0.y + v0.z * v0.z + v0.w * v0.w +
              v1.x * v1.x + v1.y * v1.y + v1.z * v1.z + v1.w * v1.w;
#pragma unroll
    for (int o = 16; o > 0; o >>= 1) s += __shfl_xor_sync(0xffffffffu, s, o);
    if (lane == 0) g_xnorm[w] = sqrtf(s);
    __half2* dst = (__half2*)(g_xh + (size_t)w * DD);
    dst[2 * lane] = __floats2half2_rn(v0.x, v0.y);
    dst[2 * lane + 1] = __floats2half2_rn(v0.z, v0.w);
    dst[64 + 2 * lane] = __floats2half2_rn(v1.x, v1.y);
    dst[64 + 2 * lane + 1] = __floats2half2_rn(v1.z, v1.w);
}

__global__ void cvtp_kernel(const float* __restrict__ prof) {
    int w = (blockIdx.x * blockDim.x + threadIdx.x) >> 5;
    int lane = threadIdx.x & 31;
    if (w >= BB * NN) return;
    const float4* src = (const float4*)(prof + (size_t)w * DD);
    float4 v0 = src[lane], v1 = src[lane + 32];
    float s = v0.x * v0.x + v0.y * v0.y + v0.z * v0.z + v0.w * v0.w +
              v1.x * v1.x + v1.y * v1.y + v1.z * v1.z + v1.w * v1.w;
#pragma unroll
    for (int o = 16; o > 0; o >>= 1) s += __shfl_xor_sync(0xffffffffu, s, o);
    if (lane == 0) g_pnorm[w] = sqrtf(s);
    __half2* dst = (__half2*)(g_ph + (size_t)w * DD);
    dst[2 * lane] = __floats2half2_rn(v0.x, v0.y);
    dst[2 * lane + 1] = __floats2half2_rn(v0.z, v0.w);
    dst[64 + 2 * lane] = __floats2half2_rn(v1.x, v1.y);
    dst[64 + 2 * lane + 1] = __floats2half2_rn(v1.z, v1.w);
}

__global__ void ptr_kernel() {
    __shared__ __half tile[32][264];
    int b = blockIdx.x >> 4, n0 = (blockIdx.x & 15) * 32;
    int tid = threadIdx.x, wid = tid >> 5, lane = tid & 31;
#pragma unroll
    for (int s = 0; s < 4; s++) {
        int idx = s * 256 + tid;
        int row = idx >> 5, c = idx & 31;
        *(uint4*)&tile[row][c * 8] =
            *(const uint4*)(g_ph + ((size_t)(b * NN + n0 + row)) * DD + c * 8);
    }
    __syncthreads();
#pragma unroll
    for (int i = 0; i < 32; i++) {
        int d = wid * 32 + i;
        if (lane < 16) {
            __half2 v = __halves2half2(tile[2 * lane][d], tile[2 * lane + 1][d]);
            ((__half2*)(g_pth + ((size_t)(b * DD + d)) * NN + n0))[lane] = v;
        }
    }
}

// ---------------- fused kernel: 512 threads, 4m x 4n warps, ldmatrix ----------------
#define ESH_B 0                      // 64 x 520 fp16 = 66560
#define XB_B 66560                   // 2 x (64 x 72 fp16) = 2 x 9216
#define PB_B 84992                   // 2 x (256 x 72 fp16) = 2 x 36864
#define PT_B 66560                   // phase 2 alias: 2 x 36864
#define PNS_B 158720                 // 512 f32
#define XNS_B 160768                 // 64 f32
#define INV_B 161024                 // 64 f32
#define RSP_B 161280                 // 256 f32
#define F_SMEM 162304

__global__ __launch_bounds__(512, 1) void cosattn_fused(
    const int* __restrict__ lens, float* __restrict__ wout, float* __restrict__ emb) {
    extern __shared__ char smc[];
    const uint32_t smb = smem_u32(smc);
    __half* Esh = (__half*)(smc + ESH_B);
    float* pns = (float*)(smc + PNS_B);
    float* xns = (float*)(smc + XNS_B);
    float* inv = (float*)(smc + INV_B);
    float* rsp = (float*)(smc + RSP_B);

    int b = blockIdx.x >> 6;
    int l0 = (blockIdx.x & 63) * 64;
    int tid = threadIdx.x;
    int wid = tid >> 5, lane = tid & 31;
    int wm = wid & 3, wn = wid >> 2;          // 4 m-warps x 4 n-warps
    int qg = lane >> 2, qt = lane & 3;
    int lm = lane >> 3, lr = lane & 7;        // ldmatrix: matrix idx / row-in-matrix

    for (int i = tid; i < NN; i += 512) pns[i] = g_pnorm[b * NN + i];
    if (tid < 64) xns[tid] = g_xnorm[(size_t)b * LL + l0 + tid];
    if (tid < 256) rsp[tid] = 0.f;
    int plen = __ldg(&lens[b]);

#define ISSUE1(it) do {                                                          \
    int _nch = (it) >> 2, _kc = (it) & 3, _bi = (it) & 1;                        \
    int _k0 = _kc * 64;                                                          \
    const __half* _xs = g_xh + ((size_t)(b * LL + l0)) * DD + _k0;               \
    {                                                                            \
        int row = tid >> 3, c = tid & 7;                                         \
        cp16(smb + XB_B + _bi * 9216 + (row * 72 + c * 8) * 2,                   \
             _xs + (size_t)row * DD + c * 8);                                    \
    }                                                                            \
    const __half* _ps = g_ph + ((size_t)(b * NN + _nch * 256)) * DD + _k0;       \
    _Pragma("unroll")                                                            \
    for (int s = 0; s < 4; s++) {                                                \
        int idx = s * 512 + tid;                                                 \
        int row = idx >> 3, c = idx & 7;                                         \
        cp16(smb + PB_B + _bi * 36864 + (row * 72 + c * 8) * 2,                  \
             _ps + (size_t)row * DD + c * 8);                                    \
    }                                                                            \
    CP_COMMIT();                                                                 \
} while (0)

    float acc[32];
#pragma unroll
    for (int i = 0; i < 32; i++) acc[i] = 0.f;

    // ldmatrix per-lane row/col offsets (matrix lm: row += (lm&1)*8, col += (lm>>1)*8)
    int a_row = wm * 16 + (lm & 1) * 8 + lr;
    int a_kof = (lm >> 1) * 8;
    int b_rof = (lm >> 1) * 8;                // n-offset selecting nt pair member
    int b_kof = (lm & 1) * 8;

    ISSUE1(0);
    for (int it = 0; it < 8; ++it) {
        if (it < 7) { ISSUE1(it + 1); CP_WAIT1(); } else { CP_WAIT0(); }
        __syncthreads();
        int bi = it & 1;
        uint32_t xb = smb + XB_B + bi * 9216;
        uint32_t pb = smb + PB_B + bi * 36864;
#pragma unroll
        for (int ks = 0; ks < 4; ks++) {
            int kk = ks * 16;
            uint32_t af[4];
            ldsm4(af, xb + (a_row * 72 + kk + a_kof) * 2);
#pragma unroll
            for (int j = 0; j < 4; j++) {
                uint32_t bq[4];
                int n = wn * 64 + (2 * j) * 8 + b_rof + lr;
                ldsm4(bq, pb + (n * 72 + kk + b_kof) * 2);
                mma_f16(&acc[(2 * j) * 4], af, bq);
                mma_f16(&acc[(2 * j + 1) * 4], af, bq + 2);
            }
        }
        if ((it & 3) == 3) {
            int nch = it >> 2;
            int r0 = wm * 16 + qg;
            float xr0 = xns[r0], xr1 = xns[r0 + 8];
            float sum0 = 0.f, sum1 = 0.f;
#pragma unroll
            for (int nt = 0; nt < 8; nt++) {
                int n = nch * 256 + wn * 64 + nt * 8 + qt * 2;
                float pn0 = pns[n], pn1 = pns[n + 1];
                float* a = &acc[nt * 4];
                float e0 = (n < plen) ? __expf(a[0] / fmaxf(xr0 * pn0, EPSV)) : 0.f;
                float e1 = (n + 1 < plen) ? __expf(a[1] / fmaxf(xr0 * pn1, EPSV)) : 0.f;
                float e2 = (n < plen) ? __expf(a[2] / fmaxf(xr1 * pn0, EPSV)) : 0.f;
                float e3 = (n + 1 < plen) ? __expf(a[3] / fmaxf(xr1 * pn1, EPSV)) : 0.f;
                sum0 += e0 + e1;
                sum1 += e2 + e3;
                *(__half2*)&Esh[r0 * 520 + n] = __floats2half2_rn(e0, e1);
                *(__half2*)&Esh[(r0 + 8) * 520 + n] = __floats2half2_rn(e2, e3);
                a[0] = a[1] = a[2] = a[3] = 0.f;
            }
#pragma unroll
            for (int o = 1; o < 4; o <<= 1) {
                sum0 += __shfl_xor_sync(0xffffffffu, sum0, o);
                sum1 += __shfl_xor_sync(0xffffffffu, sum1, o);
            }
            if (qt == 0) {
                rsp[wn * 64 + r0] += sum0;
                rsp[wn * 64 + r0 + 8] += sum1;
            }
        }
        __syncthreads();
    }

#define ISSUE2(it) do {                                                          \
    int _bi = (it) & 1;                                                          \
    const __half* _ts = g_pth + (size_t)b * DD * NN + (it) * 64;                 \
    _Pragma("unroll")                                                            \
    for (int s = 0; s < 4; s++) {                                                \
        int idx = s * 512 + tid;                                                 \
        int row = idx >> 3, c = idx & 7;                                         \
        cp16(smb + PT_B + _bi * 36864 + (row * 72 + c * 8) * 2,                  \
             _ts + (size_t)row * NN + c * 8);                                    \
    }                                                                            \
    CP_COMMIT();                                                                 \
} while (0)

    if (tid < 64)
        inv[tid] = 1.0f / (rsp[tid] + rsp[64 + tid] + rsp[128 + tid] + rsp[192 + tid]);
    ISSUE2(0);
    __syncthreads();

    // normalized weights out (overlaps cp.async flight)
    {
        const __half2* Eh2 = (const __half2*)Esh;   // row stride 260 half2
        float* wbase = wout + ((size_t)b * LL + l0) * NN;
#pragma unroll
        for (int s = 0; s < 32; s++) {
            int idx = s * 512 + tid;
            int row = idx >> 8, c2 = idx & 255;
            float2 v = __half22float2(Eh2[row * 260 + c2]);
            float iv = inv[row];
            *(float2*)(wbase + (size_t)row * NN + c2 * 2) = make_float2(v.x * iv, v.y * iv);
        }
    }

    // ---- phase 2: emb = (E @ P) * inv, K=512 over 8 chunks of 64 ----
    for (int it = 0; it < 8; ++it) {
        if (it < 7) { ISSUE2(it + 1); CP_WAIT1(); } else { CP_WAIT0(); }
        __syncthreads();
        int bi = it & 1;
        uint32_t ptb = smb + PT_B + bi * 36864;
        int nb = it * 64;
#pragma unroll
        for (int ks = 0; ks < 4; ks++) {
            int kk = ks * 16;
            uint32_t af[4];
            ldsm4(af, smb + ESH_B + (a_row * 520 + nb + kk + a_kof) * 2);
#pragma unroll
            for (int j = 0; j < 4; j++) {
                uint32_t bq[4];
                int d = wn * 64 + (2 * j) * 8 + b_rof + lr;
                ldsm4(bq, ptb + (d * 72 + kk + b_kof) * 2);
                mma_f16(&acc[(2 * j) * 4], af, bq);
                mma_f16(&acc[(2 * j + 1) * 4], af, bq + 2);
            }
        }
        __syncthreads();
    }

    // epilogue: emb scaled by inv
    {
        int r0 = wm * 16 + qg;
        float iv0 = inv[r0], iv1 = inv[r0 + 8];
#pragma unroll
        for (int nt = 0; nt < 8; nt++) {
            int d = wn * 64 + nt * 8 + qt * 2;
            const float* a = &acc[nt * 4];
            float* e0 = emb + ((size_t)b * LL + l0 + r0) * DD + d;
            float* e1 = emb + ((size_t)b * LL + l0 + r0 + 8) * DD + d;
            *(float2*)e0 = make_float2(a[0] * iv0, a[1] * iv0);
            *(float2*)e1 = make_float2(a[2] * iv1, a[3] * iv1);
        }
    }
}

extern "C" void kernel_launch(void* const* d_in, const int* in_sizes, int n_in,
                              void* d_out, int out_size) {
    const float* x = (const float*)d_in[0];
    const float* prof = (const float*)d_in[1];
    const int* lens = (const int*)d_in[2];
    float* emb = (float*)d_out;
    float* wout = (float*)d_out + (size_t)BB * LL * DD;

    cudaFuncSetAttribute(cosattn_fused, cudaFuncAttributeMaxDynamicSharedMemorySize, F_SMEM);

    cvtx_kernel<<<(BB * LL) / 8, 256>>>(x);
    cvtp_kernel<<<(BB * NN) / 8, 256>>>(prof);
    ptr_kernel<<<BB * (NN / 32), 256>>>();
    cosattn_fused<<<BB * (LL / 64), 512, F_SMEM>>>(lens, wout, emb);
}

// round 15
// speedup vs baseline: 1.0057x; 1.0057x over previous
#include <cuda_runtime.h>
#include <cuda_fp16.h>
#include <math.h>
#include <float.h>
#include <stdint.h>

#define BB 16
#define LL 4096
#define NN 512
#define DD 256
#define EPSV 1e-8f

__device__ float g_pnorm[BB * NN];
__device__ float g_xnorm[BB * LL];
__device__ __half g_xh[BB * LL * DD];    // 32MB fp16 X
__device__ __half g_ph[BB * NN * DD];    // 4MB fp16 P [b][n][d]
__device__ __half g_pth[BB * DD * NN];   // 4MB fp16 P^T [b][d][n]

__device__ __forceinline__ uint32_t smem_u32(const void* p) {
    uint32_t a;
    asm("{ .reg .u64 t; cvta.to.shared.u64 t, %1; cvt.u32.u64 %0, t; }" : "=r"(a) : "l"(p));
    return a;
}
__device__ __forceinline__ void cp16(uint32_t dst, const void* src) {
    asm volatile("cp.async.ca.shared.global [%0], [%1], 16;" :: "r"(dst), "l"(src));
}
#define CP_COMMIT() asm volatile("cp.async.commit_group;" ::: "memory")
#define CP_WAIT1()  asm volatile("cp.async.wait_group 1;" ::: "memory")
#define CP_WAIT0()  asm volatile("cp.async.wait_group 0;" ::: "memory")

__device__ __forceinline__ void ldsm4(uint32_t* r, uint32_t addr) {
    asm volatile("ldmatrix.sync.aligned.m8n8.x4.shared.b16 {%0,%1,%2,%3}, [%4];"
        : "=r"(r[0]), "=r"(r[1]), "=r"(r[2]), "=r"(r[3]) : "r"(addr));
}

__device__ __forceinline__ void mma_f16(float* d, const uint32_t* a, const uint32_t* b) {
    asm volatile(
        "mma.sync.aligned.m16n8k16.row.col.f32.f16.f16.f32 "
        "{%0,%1,%2,%3}, {%4,%5,%6,%7}, {%8,%9}, {%0,%1,%2,%3};"
        : "+f"(d[0]), "+f"(d[1]), "+f"(d[2]), "+f"(d[3])
        : "r"(a[0]), "r"(a[1]), "r"(a[2]), "r"(a[3]), "r"(b[0]), "r"(b[1]));
}

// ---------------- prepasses ----------------
__global__ void cvtx_kernel(const float* __restrict__ x) {
    int w = (blockIdx.x * blockDim.x + threadIdx.x) >> 5;
    int lane = threadIdx.x & 31;
    if (w >= BB * LL) return;
    const float4* src = (const float4*)(x + (size_t)w * DD);
    float4 v0 = src[lane], v1 = src[lane + 32];
    float s = v0.x * v0.x + v0.y * v0.y + v0.z * v0.z + v0.w * v0.w +
              v1.x * v1.x + v1.y * v1.y + v1.z * v1.z + v1.w * v1.w;
#pragma unroll
    for (int o = 16; o > 0; o >>= 1) s += __shfl_xor_sync(0xffffffffu, s, o);
    if (lane == 0) g_xnorm[w] = sqrtf(s);
    __half2* dst = (__half2*)(g_xh + (size_t)w * DD);
    dst[2 * lane] = __floats2half2_rn(v0.x, v0.y);
    dst[2 * lane + 1] = __floats2half2_rn(v0.z, v0.w);
    dst[64 + 2 * lane] = __floats2half2_rn(v1.x, v1.y);
    dst[64 + 2 * lane + 1] = __floats2half2_rn(v1.z, v1.w);
}

__global__ void cvtp_kernel(const float* __restrict__ prof) {
    int w = (blockIdx.x * blockDim.x + threadIdx.x) >> 5;
    int lane = threadIdx.x & 31;
    if (w >= BB * NN) return;
    const float4* src = (const float4*)(prof + (size_t)w * DD);
    float4 v0 = src[lane], v1 = src[lane + 32];
    float s = v0.x * v0.x + v0.y * v0.y + v0.z * v0.z + v0.w * v0.w +
              v1.x * v1.x + v1.y * v1.y + v1.z * v1.z + v1.w * v1.w;
#pragma unroll
    for (int o = 16; o > 0; o >>= 1) s += __shfl_xor_sync(0xffffffffu, s, o);
    if (lane == 0) g_pnorm[w] = sqrtf(s);
    __half2* dst = (__half2*)(g_ph + (size_t)w * DD);
    dst[2 * lane] = __floats2half2_rn(v0.x, v0.y);
    dst[2 * lane + 1] = __floats2half2_rn(v0.z, v0.w);
    dst[64 + 2 * lane] = __floats2half2_rn(v1.x, v1.y);
    dst[64 + 2 * lane + 1] = __floats2half2_rn(v1.z, v1.w);
}

__global__ void ptr_kernel() {
    __shared__ __half tile[32][264];
    int b = blockIdx.x >> 4, n0 = (blockIdx.x & 15) * 32;
    int tid = threadIdx.x, wid = tid >> 5, lane = tid & 31;
#pragma unroll
    for (int s = 0; s < 4; s++) {
        int idx = s * 256 + tid;
        int row = idx >> 5, c = idx & 31;
        *(uint4*)&tile[row][c * 8] =
            *(const uint4*)(g_ph + ((size_t)(b * NN + n0 + row)) * DD + c * 8);
    }
    __syncthreads();
#pragma unroll
    for (int i = 0; i < 32; i++) {
        int d = wid * 32 + i;
        if (lane < 16) {
            __half2 v = __halves2half2(tile[2 * lane][d], tile[2 * lane + 1][d]);
            ((__half2*)(g_pth + ((size_t)(b * DD + d)) * NN + n0))[lane] = v;
        }
    }
}

// ---------------- fused kernel: 256 threads, 2m x 4n warps, ldmatrix + frag pipeline ----
#define ESH_B 0                      // 64 x 520 fp16 = 66560
#define XB_B 66560                   // 2 x (64 x 72 fp16) = 2 x 9216
#define PB_B 84992                   // 2 x (256 x 72 fp16) = 2 x 36864
#define PT_B 66560                   // phase 2 alias: 2 x 36864
#define PNS_B 158720                 // 512 f32
#define XNS_B 160768                 // 64 f32
#define INV_B 161024                 // 64 f32
#define RSP_B 161280                 // 256 f32
#define F_SMEM 162304

__global__ __launch_bounds__(256, 1) void cosattn_fused(
    const int* __restrict__ lens, float* __restrict__ wout, float* __restrict__ emb) {
    extern __shared__ char smc[];
    const uint32_t smb = smem_u32(smc);
    __half* Esh = (__half*)(smc + ESH_B);
    float* pns = (float*)(smc + PNS_B);
    float* xns = (float*)(smc + XNS_B);
    float* inv = (float*)(smc + INV_B);
    float* rsp = (float*)(smc + RSP_B);

    int b = blockIdx.x >> 6;
    int l0 = (blockIdx.x & 63) * 64;
    int tid = threadIdx.x;
    int wid = tid >> 5, lane = tid & 31;
    int wm = wid & 1, wn = wid >> 1;          // 2 m-warps (32 rows) x 4 n-warps (64 cols)
    int qg = lane >> 2, qt = lane & 3;
    int lm = lane >> 3, lr = lane & 7;

    for (int i = tid; i < NN; i += 256) pns[i] = g_pnorm[b * NN + i];
    if (tid < 64) xns[tid] = g_xnorm[(size_t)b * LL + l0 + tid];
    rsp[tid] = 0.f;
    int plen = __ldg(&lens[b]);

#define ISSUE1(it) do {                                                          \
    int _nch = (it) >> 2, _kc = (it) & 3, _bi = (it) & 1;                        \
    int _k0 = _kc * 64;                                                          \
    const __half* _xs = g_xh + ((size_t)(b * LL + l0)) * DD + _k0;               \
    _Pragma("unroll")                                                            \
    for (int s = 0; s < 2; s++) {                                                \
        int idx = s * 256 + tid;                                                 \
        int row = idx >> 3, c = idx & 7;                                         \
        cp16(smb + XB_B + _bi * 9216 + (row * 72 + c * 8) * 2,                   \
             _xs + (size_t)row * DD + c * 8);                                    \
    }                                                                            \
    const __half* _ps = g_ph + ((size_t)(b * NN + _nch * 256)) * DD + _k0;       \
    _Pragma("unroll")                                                            \
    for (int s = 0; s < 8; s++) {                                                \
        int idx = s * 256 + tid;                                                 \
        int row = idx >> 3, c = idx & 7;                                         \
        cp16(smb + PB_B + _bi * 36864 + (row * 72 + c * 8) * 2,                  \
             _ps + (size_t)row * DD + c * 8);                                    \
    }                                                                            \
    CP_COMMIT();                                                                 \
} while (0)

    float acc[64];
#pragma unroll
    for (int i = 0; i < 64; i++) acc[i] = 0.f;

    // ldmatrix lane offsets
    int a_row0 = wm * 32 + (lm & 1) * 8 + lr;   // mt=0 base; mt=1 adds 16
    int a_kof = (lm >> 1) * 8;
    int b_rof = (lm >> 1) * 8;
    int b_kof = (lm & 1) * 8;

    ISSUE1(0);
    for (int it = 0; it < 8; ++it) {
        if (it < 7) { ISSUE1(it + 1); CP_WAIT1(); } else { CP_WAIT0(); }
        __syncthreads();
        int bi = it & 1;
        uint32_t xb = smb + XB_B + bi * 9216;
        uint32_t pb = smb + PB_B + bi * 36864;

        uint32_t af[2][2][4], bq[2][4][4];
        // prefetch ks=0
        ldsm4(af[0][0], xb + (a_row0 * 72 + a_kof) * 2);
        ldsm4(af[0][1], xb + ((a_row0 + 16) * 72 + a_kof) * 2);
#pragma unroll
        for (int j = 0; j < 4; j++) {
            int n = wn * 64 + j * 16 + b_rof + lr;
            ldsm4(bq[0][j], pb + (n * 72 + b_kof) * 2);
        }
#pragma unroll
        for (int ks = 0; ks < 4; ks++) {
            int cur = ks & 1, nxt = cur ^ 1;
            if (ks < 3) {
                int kk = (ks + 1) * 16;
                ldsm4(af[nxt][0], xb + (a_row0 * 72 + kk + a_kof) * 2);
                ldsm4(af[nxt][1], xb + ((a_row0 + 16) * 72 + kk + a_kof) * 2);
#pragma unroll
                for (int j = 0; j < 4; j++) {
                    int n = wn * 64 + j * 16 + b_rof + lr;
                    ldsm4(bq[nxt][j], pb + (n * 72 + kk + b_kof) * 2);
                }
            }
#pragma unroll
            for (int j = 0; j < 4; j++) {
#pragma unroll
                for (int mt = 0; mt < 2; mt++) {
                    mma_f16(&acc[(mt * 8 + 2 * j) * 4], af[cur][mt], bq[cur][j]);
                    mma_f16(&acc[(mt * 8 + 2 * j + 1) * 4], af[cur][mt], bq[cur][j] + 2);
                }
            }
        }

        if ((it & 3) == 3) {
            int nch = it >> 2;
#pragma unroll
            for (int mt = 0; mt < 2; mt++) {
                int r0 = wm * 32 + mt * 16 + qg;
                float xr0 = xns[r0], xr1 = xns[r0 + 8];
                float sum0 = 0.f, sum1 = 0.f;
#pragma unroll
                for (int nt = 0; nt < 8; nt++) {
                    int n = nch * 256 + wn * 64 + nt * 8 + qt * 2;
                    float pn0 = pns[n], pn1 = pns[n + 1];
                    float* a = &acc[(mt * 8 + nt) * 4];
                    float e0 = (n < plen) ? __expf(a[0] / fmaxf(xr0 * pn0, EPSV)) : 0.f;
                    float e1 = (n + 1 < plen) ? __expf(a[1] / fmaxf(xr0 * pn1, EPSV)) : 0.f;
                    float e2 = (n < plen) ? __expf(a[2] / fmaxf(xr1 * pn0, EPSV)) : 0.f;
                    float e3 = (n + 1 < plen) ? __expf(a[3] / fmaxf(xr1 * pn1, EPSV)) : 0.f;
                    sum0 += e0 + e1;
                    sum1 += e2 + e3;
                    *(__half2*)&Esh[r0 * 520 + n] = __floats2half2_rn(e0, e1);
                    *(__half2*)&Esh[(r0 + 8) * 520 + n] = __floats2half2_rn(e2, e3);
                    a[0] = a[1] = a[2] = a[3] = 0.f;
                }
#pragma unroll
                for (int o = 1; o < 4; o <<= 1) {
                    sum0 += __shfl_xor_sync(0xffffffffu, sum0, o);
                    sum1 += __shfl_xor_sync(0xffffffffu, sum1, o);
                }
                if (qt == 0) {
                    rsp[wn * 64 + r0] += sum0;
                    rsp[wn * 64 + r0 + 8] += sum1;
                }
            }
        }
        __syncthreads();
    }

#define ISSUE2(it) do {                                                          \
    int _bi = (it) & 1;                                                          \
    const __half* _ts = g_pth + (size_t)b * DD * NN + (it) * 64;                 \
    _Pragma("unroll")                                                            \
    for (int s = 0; s < 8; s++) {                                                \
        int idx = s * 256 + tid;                                                 \
        int row = idx >> 3, c = idx & 7;                                         \
        cp16(smb + PT_B + _bi * 36864 + (row * 72 + c * 8) * 2,                  \
             _ts + (size_t)row * NN + c * 8);                                    \
    }                                                                            \
    CP_COMMIT();                                                                 \
} while (0)

    if (tid < 64)
        inv[tid] = 1.0f / (rsp[tid] + rsp[64 + tid] + rsp[128 + tid] + rsp[192 + tid]);
    ISSUE2(0);
    __syncthreads();

    // normalized weights out (overlaps cp.async flight)
    {
        const __half2* Eh2 = (const __half2*)Esh;   // row stride 260 half2
        float* wbase = wout + ((size_t)b * LL + l0) * NN;
#pragma unroll
        for (int s = 0; s < 64; s++) {
            int idx = s * 256 + tid;
            int row = idx >> 8, c2 = idx & 255;
            float2 v = __half22float2(Eh2[row * 260 + c2]);
            float iv = inv[row];
            *(float2*)(wbase + (size_t)row * NN + c2 * 2) = make_float2(v.x * iv, v.y * iv);
        }
    }

    // ---- phase 2: emb = (E @ P) * inv, K=512 over 8 chunks of 64 ----
    for (int it = 0; it < 8; ++it) {
        if (it < 7) { ISSUE2(it + 1); CP_WAIT1(); } else { CP_WAIT0(); }
        __syncthreads();
        int bi = it & 1;
        uint32_t ptb = smb + PT_B + bi * 36864;
        int nb = it * 64;

        uint32_t af[2][2][4], bq[2][4][4];
        ldsm4(af[0][0], smb + ESH_B + (a_row0 * 520 + nb + a_kof) * 2);
        ldsm4(af[0][1], smb + ESH_B + ((a_row0 + 16) * 520 + nb + a_kof) * 2);
#pragma unroll
        for (int j = 0; j < 4; j++) {
            int d = wn * 64 + j * 16 + b_rof + lr;
            ldsm4(bq[0][j], ptb + (d * 72 + b_kof) * 2);
        }
#pragma unroll
        for (int ks = 0; ks < 4; ks++) {
            int cur = ks & 1, nxt = cur ^ 1;
            if (ks < 3) {
                int kk = (ks + 1) * 16;
                ldsm4(af[nxt][0], smb + ESH_B + (a_row0 * 520 + nb + kk + a_kof) * 2);
                ldsm4(af[nxt][1], smb + ESH_B + ((a_row0 + 16) * 520 + nb + kk + a_kof) * 2);
#pragma unroll
                for (int j = 0; j < 4; j++) {
                    int d = wn * 64 + j * 16 + b_rof + lr;
                    ldsm4(bq[nxt][j], ptb + (d * 72 + kk + b_kof) * 2);
                }
            }
#pragma unroll
            for (int j = 0; j < 4; j++) {
#pragma unroll
                for (int mt = 0; mt < 2; mt++) {
                    mma_f16(&acc[(mt * 8 + 2 * j) * 4], af[cur][mt], bq[cur][j]);
                    mma_f16(&acc[(mt * 8 + 2 * j + 1) * 4], af[cur][mt], bq[cur][j] + 2);
                }
            }
        }
        __syncthreads();
    }

    // epilogue: emb scaled by inv
#pragma unroll
    for (int mt = 0; mt < 2; mt++) {
        int r0 = wm * 32 + mt * 16 + qg;
        float iv0 = inv[r0], iv1 = inv[r0 + 8];
#pragma unroll
        for (int nt = 0; nt < 8; nt++) {
            int d = wn * 64 + nt * 8 + qt * 2;
            const float* a = &acc[(mt * 8 + nt) * 4];
            float* e0 = emb + ((size_t)b * LL + l0 + r0) * DD + d;
            float* e1 = emb + ((size_t)b * LL + l0 + r0 + 8) * DD + d;
            *(float2*)e0 = make_float2(a[0] * iv0, a[1] * iv0);
            *(float2*)e1 = make_float2(a[2] * iv1, a[3] * iv1);
        }
    }
}

extern "C" void kernel_launch(void* const* d_in, const int* in_sizes, int n_in,
                              void* d_out, int out_size) {
    const float* x = (const float*)d_in[0];
    const float* prof = (const float*)d_in[1];
    const int* lens = (const int*)d_in[2];
    float* emb = (float*)d_out;
    float* wout = (float*)d_out + (size_t)BB * LL * DD;

    cudaFuncSetAttribute(cosattn_fused, cudaFuncAttributeMaxDynamicSharedMemorySize, F_SMEM);

    cvtx_kernel<<<(BB * LL) / 8, 256>>>(x);
    cvtp_kernel<<<(BB * NN) / 8, 256>>>(prof);
    ptr_kernel<<<BB * (NN / 32), 256>>>();
    cosattn_fused<<<BB * (LL / 64), 256, F_SMEM>>>(lens, wout, emb);
}